// round 1
// baseline (speedup 1.0000x reference)
#include <cuda_runtime.h>
#include <cuda_bf16.h>

// Problem constants
#define NN   50000
#define EE   800000
#define ETOT 850000   // EE + NN self loops
#define HD   64       // hidden dim

// ---------------- scratch (static device globals; no allocation) ------------
static __device__ int      g_src[ETOT];
static __device__ int      g_dst[ETOT];
static __device__ float    g_e[ETOT];
static __device__ float    g_h[NN * HD];     // transformed features (reused both layers)
static __device__ float    g_agg1[NN * HD];  // layer-1 aggregation result (seeded with b1)
static __device__ float    g_as[NN];
static __device__ float    g_ad[NN];
static __device__ unsigned g_menc[NN];
static __device__ float    g_den[NN];
static __device__ int      g_is64;

// ---------------- helpers ---------------------------------------------------
__device__ __forceinline__ unsigned enc_f(float f) {
    unsigned u = __float_as_uint(f);
    return (u & 0x80000000u) ? ~u : (u | 0x80000000u);
}
__device__ __forceinline__ float dec_f(unsigned u) {
    return (u & 0x80000000u) ? __uint_as_float(u ^ 0x80000000u) : __uint_as_float(~u);
}
__device__ __forceinline__ void red_add_v4(float* p, float a, float b, float c, float d) {
    asm volatile("red.global.add.v4.f32 [%0], {%1, %2, %3, %4};"
                 :: "l"(p), "f"(a), "f"(b), "f"(c), "f"(d) : "memory");
}

// ---------------- dtype detection + edge decode -----------------------------
__global__ void detect_kernel(const unsigned* __restrict__ w) {
    __shared__ int s;
    if (threadIdx.x == 0) s = 0;
    __syncthreads();
    // If data is int64 (values < 2^31), every odd 32-bit word is 0.
    // If int32, P(256 consecutive sampled src values == 0) ~ 0.
    if (w[2 * threadIdx.x + 1] != 0u) atomicOr(&s, 1);
    __syncthreads();
    if (threadIdx.x == 0) g_is64 = (s == 0);
}

__global__ void decode_kernel(const void* __restrict__ ei) {
    int i = blockIdx.x * blockDim.x + threadIdx.x;
    if (i >= ETOT) return;
    if (i >= EE) {                       // self loops appended at the end
        g_src[i] = i - EE;
        g_dst[i] = i - EE;
        return;
    }
    if (g_is64) {
        const long long* p = (const long long*)ei;
        g_src[i] = (int)p[i];
        g_dst[i] = (int)p[EE + i];
    } else {
        const int* p = (const int*)ei;
        g_src[i] = p[i];
        g_dst[i] = p[EE + i];
    }
}

// ---------------- init: seed agg with bias, reset softmax scratch -----------
__global__ void init_kernel(float* __restrict__ agg, const float* __restrict__ bias) {
    int i = blockIdx.x * blockDim.x + threadIdx.x;
    if (i < NN * HD) agg[i] = bias[i & 63];
    if (i < NN) { g_menc[i] = 0u; g_den[i] = 0.0f; }
}

// ---------------- GEMM: h = x @ W^T, fused alpha epilogue -------------------
// Block: 256 threads, 64 rows x 64 cols tile, 4x4 micro-tile per thread.
// Optional fused ReLU on the input load (layer-2 reads relu(agg1)).
template <int K, bool RELU>
__global__ void gemm_kernel(const float* __restrict__ x, const float* __restrict__ W,
                            const float* __restrict__ asrc, const float* __restrict__ adst,
                            float* __restrict__ h, float* __restrict__ out_as,
                            float* __restrict__ out_ad)
{
    extern __shared__ float sm[];
    float* Wt = sm;               // [K][64]  (transposed W)
    float* xs = sm + K * 64;      // [64][K+4]
    const int KP = K + 4;

    int tid  = threadIdx.x;
    int row0 = blockIdx.x * 64;

    // Load W transposed: Wt[k][c] = W[c][k]. Writes conflict-free (c fast).
    for (int i = tid; i < 64 * K; i += 256) {
        int c = i & 63, k = i >> 6;
        Wt[k * 64 + c] = W[c * K + k];
    }
    // Load 64 input rows (float4 along K), zero-fill OOB rows.
    for (int i = tid; i < 64 * (K / 4); i += 256) {
        int r = i / (K / 4), kq = i % (K / 4);
        int row = row0 + r;
        float4 v = make_float4(0.f, 0.f, 0.f, 0.f);
        if (row < NN) {
            v = *reinterpret_cast<const float4*>(&x[(long)row * K + kq * 4]);
            if (RELU) {
                v.x = fmaxf(v.x, 0.f); v.y = fmaxf(v.y, 0.f);
                v.z = fmaxf(v.z, 0.f); v.w = fmaxf(v.w, 0.f);
            }
        }
        *reinterpret_cast<float4*>(&xs[r * KP + kq * 4]) = v;
    }
    __syncthreads();

    int tx = tid & 15;   // col group: cols tx*4 .. tx*4+3
    int ty = tid >> 4;   // row group: rows ty*4 .. ty*4+3

    float acc[4][4];
#pragma unroll
    for (int i = 0; i < 4; i++)
#pragma unroll
        for (int j = 0; j < 4; j++) acc[i][j] = 0.f;

    const float* xb = &xs[(ty * 4) * KP];
#pragma unroll 4
    for (int k = 0; k < K; k++) {
        float a0 = xb[k];
        float a1 = xb[KP + k];
        float a2 = xb[2 * KP + k];
        float a3 = xb[3 * KP + k];
        float4 b = *reinterpret_cast<const float4*>(&Wt[k * 64 + tx * 4]);
        acc[0][0] += a0 * b.x; acc[0][1] += a0 * b.y; acc[0][2] += a0 * b.z; acc[0][3] += a0 * b.w;
        acc[1][0] += a1 * b.x; acc[1][1] += a1 * b.y; acc[1][2] += a1 * b.z; acc[1][3] += a1 * b.w;
        acc[2][0] += a2 * b.x; acc[2][1] += a2 * b.y; acc[2][2] += a2 * b.z; acc[2][3] += a2 * b.w;
        acc[3][0] += a3 * b.x; acc[3][1] += a3 * b.y; acc[3][2] += a3 * b.z; acc[3][3] += a3 * b.w;
    }

    // Epilogue: store h, compute per-row alpha partials, reduce over the 16
    // col-group lanes (lanes sharing a row live in one 16-lane half-warp).
    float c0 = asrc[tx * 4 + 0], c1 = asrc[tx * 4 + 1], c2 = asrc[tx * 4 + 2], c3 = asrc[tx * 4 + 3];
    float d0 = adst[tx * 4 + 0], d1 = adst[tx * 4 + 1], d2 = adst[tx * 4 + 2], d3 = adst[tx * 4 + 3];

    float sA[4], sD[4];
#pragma unroll
    for (int i = 0; i < 4; i++) {
        int row = row0 + ty * 4 + i;
        float4 v = make_float4(acc[i][0], acc[i][1], acc[i][2], acc[i][3]);
        if (row < NN)
            *reinterpret_cast<float4*>(&h[(long)row * HD + tx * 4]) = v;
        sA[i] = v.x * c0 + v.y * c1 + v.z * c2 + v.w * c3;
        sD[i] = v.x * d0 + v.y * d1 + v.z * d2 + v.w * d3;
    }
#pragma unroll
    for (int off = 8; off >= 1; off >>= 1) {
#pragma unroll
        for (int i = 0; i < 4; i++) {
            sA[i] += __shfl_xor_sync(0xffffffffu, sA[i], off);
            sD[i] += __shfl_xor_sync(0xffffffffu, sD[i], off);
        }
    }
    if (tx == 0) {
#pragma unroll
        for (int i = 0; i < 4; i++) {
            int row = row0 + ty * 4 + i;
            if (row < NN) { out_as[row] = sA[i]; out_ad[row] = sD[i]; }
        }
    }
}

// ---------------- edge passes -----------------------------------------------
__global__ void epass1_kernel() {
    int i = blockIdx.x * blockDim.x + threadIdx.x;
    if (i >= ETOT) return;
    int s = g_src[i], d = g_dst[i];
    float e = g_as[s] + g_ad[d];
    e = e > 0.f ? e : 0.2f * e;          // LeakyReLU(0.2)
    g_e[i] = e;
    atomicMax(&g_menc[d], enc_f(e));
}

__global__ void epass2_kernel() {
    int i = blockIdx.x * blockDim.x + threadIdx.x;
    if (i >= ETOT) return;
    int d = g_dst[i];
    float m  = dec_f(g_menc[d]);
    float ex = expf(g_e[i] - m);
    g_e[i] = ex;
    atomicAdd(&g_den[d], ex);
}

// 16 threads per edge, each handles 4 contiguous output channels.
__global__ void epass3_kernel(const float* __restrict__ h, float* __restrict__ agg) {
    int gid  = blockIdx.x * blockDim.x + threadIdx.x;
    int edge = gid >> 4;
    int q    = gid & 15;
    if (edge >= ETOT) return;
    int s = g_src[edge], d = g_dst[edge];
    float coef = g_e[edge] / g_den[d];
    float4 v = *reinterpret_cast<const float4*>(&h[(long)s * HD + q * 4]);
    red_add_v4(&agg[(long)d * HD + q * 4], coef * v.x, coef * v.y, coef * v.z, coef * v.w);
}

// ---------------- launch -----------------------------------------------------
extern "C" void kernel_launch(void* const* d_in, const int* in_sizes, int n_in,
                              void* d_out, int out_size)
{
    const float* x   = (const float*)d_in[0];
    const void*  ei  = d_in[1];
    const float* W1  = (const float*)d_in[2];
    const float* a1s = (const float*)d_in[3];
    const float* a1d = (const float*)d_in[4];
    const float* b1  = (const float*)d_in[5];
    const float* W2  = (const float*)d_in[6];
    const float* a2s = (const float*)d_in[7];
    const float* a2d = (const float*)d_in[8];
    const float* b2  = (const float*)d_in[9];
    float* out = (float*)d_out;

    // resolve device-global scratch addresses for kernel params
    float *p_h, *p_agg1, *p_as, *p_ad;
    cudaGetSymbolAddress((void**)&p_h, g_h);
    cudaGetSymbolAddress((void**)&p_agg1, g_agg1);
    cudaGetSymbolAddress((void**)&p_as, g_as);
    cudaGetSymbolAddress((void**)&p_ad, g_ad);

    const int SMEM128 = (128 * 64 + 64 * (128 + 4)) * 4;  // 66560 B
    const int SMEM64  = (64 * 64 + 64 * (64 + 4)) * 4;    // 33792 B
    cudaFuncSetAttribute(gemm_kernel<128, false>, cudaFuncAttributeMaxDynamicSharedMemorySize, SMEM128);
    cudaFuncSetAttribute(gemm_kernel<64, true>,   cudaFuncAttributeMaxDynamicSharedMemorySize, SMEM64);

    const int TB = 256;
    const int GB_E    = (ETOT + TB - 1) / TB;
    const int GB_E16  = (ETOT * 16 + TB - 1) / TB;
    const int GB_INIT = (NN * HD + TB - 1) / TB;
    const int GB_GEMM = (NN + 63) / 64;

    // decode edges (dtype-robust)
    detect_kernel<<<1, 256>>>((const unsigned*)ei);
    decode_kernel<<<GB_E, TB>>>(ei);

    // ---- layer 1 ----
    init_kernel<<<GB_INIT, TB>>>(p_agg1, b1);
    gemm_kernel<128, false><<<GB_GEMM, TB, SMEM128>>>(x, W1, a1s, a1d, p_h, p_as, p_ad);
    epass1_kernel<<<GB_E, TB>>>();
    epass2_kernel<<<GB_E, TB>>>();
    epass3_kernel<<<GB_E16, TB>>>(p_h, p_agg1);

    // ---- layer 2 ----
    init_kernel<<<GB_INIT, TB>>>(out, b2);
    gemm_kernel<64, true><<<GB_GEMM, TB, SMEM64>>>(p_agg1, W2, a2s, a2d, p_h, p_as, p_ad);
    epass1_kernel<<<GB_E, TB>>>();
    epass2_kernel<<<GB_E, TB>>>();
    epass3_kernel<<<GB_E16, TB>>>(p_h, out);
}

// round 5
// speedup vs baseline: 1.4571x; 1.4571x over previous
#include <cuda_runtime.h>
#include <cuda_bf16.h>

// Problem constants
#define NN   50000
#define EE   800000
#define ETOT 850000   // EE + NN self loops
#define HD   64
#define NBLK 49       // ceil(NN / 1024)

// ---------------- scratch (static device globals; no allocation) ------------
static __device__ int   g_src[ETOT];
static __device__ int   g_dst[ETOT];
static __device__ int   g_csrc[ETOT];     // CSR-ordered src indices
static __device__ int   g_deg[NN];
static __device__ int   g_off[NN + 1];
static __device__ int   g_cur[NN];
static __device__ int   g_part[64];
static __device__ float g_h[NN * HD];     // transformed features
static __device__ float g_agg1[NN * HD];  // layer-1 output (pre-ReLU, incl. bias)
static __device__ float g_as[NN];
static __device__ float g_ad[NN];
static __device__ float g_Wt1[128 * 64];  // W1 transposed: [k][c]
static __device__ float g_Wt2[64 * 64];   // W2 transposed
static __device__ int   g_is64;

// ---------------- setup kernels ---------------------------------------------
__global__ void zero_kernel() {
    int i = blockIdx.x * blockDim.x + threadIdx.x;
    if (i < NN) { g_deg[i] = 0; g_cur[i] = 0; }
}

__global__ void detect_kernel(const unsigned* __restrict__ w) {
    __shared__ int s;
    if (threadIdx.x == 0) s = 0;
    __syncthreads();
    // int64 values < 2^31 -> every odd 32-bit word is 0.
    if (w[2 * threadIdx.x + 1] != 0u) atomicOr(&s, 1);
    __syncthreads();
    if (threadIdx.x == 0) g_is64 = (s == 0);
}

__global__ void decode_kernel(const void* __restrict__ ei) {
    int i = blockIdx.x * blockDim.x + threadIdx.x;
    if (i >= ETOT) return;
    int s, d;
    if (i >= EE) { s = i - EE; d = i - EE; }     // self loops
    else if (g_is64) {
        const long long* p = (const long long*)ei;
        s = (int)p[i]; d = (int)p[EE + i];
    } else {
        const int* p = (const int*)ei;
        s = p[i]; d = p[EE + i];
    }
    g_src[i] = s; g_dst[i] = d;
    atomicAdd(&g_deg[d], 1);
}

// 3-pass exclusive scan of g_deg -> g_off
__global__ void scanA_kernel() {
    __shared__ int sm[1024];
    int tid = threadIdx.x;
    int i = blockIdx.x * 1024 + tid;
    int v = (i < NN) ? g_deg[i] : 0;
    sm[tid] = v;
    __syncthreads();
    for (int off = 1; off < 1024; off <<= 1) {
        int t = (tid >= off) ? sm[tid - off] : 0;
        __syncthreads();
        sm[tid] += t;
        __syncthreads();
    }
    if (i < NN) g_off[i + 1] = sm[tid];
    if (tid == 1023) g_part[blockIdx.x] = sm[1023];
}
__global__ void scanB_kernel() {
    if (threadIdx.x == 0) {
        int acc = 0;
        for (int b = 0; b < NBLK; b++) { int t = g_part[b]; g_part[b] = acc; acc += t; }
    }
}
__global__ void scanC_kernel() {
    int i = blockIdx.x * 1024 + threadIdx.x;
    if (i < NN) g_off[i + 1] += g_part[blockIdx.x];
    if (i == 0) g_off[0] = 0;
}

__global__ void scatter_kernel() {
    int i = blockIdx.x * blockDim.x + threadIdx.x;
    if (i >= ETOT) return;
    int d = g_dst[i];
    int pos = g_off[d] + atomicAdd(&g_cur[d], 1);
    g_csrc[pos] = g_src[i];
}

// one-time weight transpose: Wt[k][c] = W[c][k]
__global__ void wtr_kernel(const float* __restrict__ W1, const float* __restrict__ W2) {
    int i = blockIdx.x * blockDim.x + threadIdx.x;
    if (i < 128 * 64) { int k = i % 128, c = i / 128; g_Wt1[k * 64 + c] = W1[c * 128 + k]; }
    if (i < 64 * 64)  { int k = i % 64,  c = i / 64;  g_Wt2[k * 64 + c] = W2[c * 64 + k]; }
}

// ---------------- GEMM: h = x @ W^T, fused alpha epilogue -------------------
// 64x64 tile / block of 256 threads, 4x4 micro-tile, K tiled by 64.
// Wt is pre-transposed in global: Wt[k*64 + c].
template <int K, bool RELU>
__global__ void gemm_kernel(const float* __restrict__ x, const float* __restrict__ Wt,
                            const float* __restrict__ asrc, const float* __restrict__ adst,
                            float* __restrict__ h, float* __restrict__ out_as,
                            float* __restrict__ out_ad)
{
    constexpr int KT = 64;
    constexpr int KTP = KT + 4;
    __shared__ float sW[KT * 64];
    __shared__ float sx[64 * KTP];

    int tid  = threadIdx.x;
    int row0 = blockIdx.x * 64;
    int tx = tid & 15;   // cols tx*4 .. tx*4+3
    int ty = tid >> 4;   // rows ty*4 .. ty*4+3

    float acc[4][4];
#pragma unroll
    for (int i = 0; i < 4; i++)
#pragma unroll
        for (int j = 0; j < 4; j++) acc[i][j] = 0.f;

    for (int kt = 0; kt < K; kt += KT) {
        // W tile: coalesced global read, conflict-free smem write
        for (int i = tid; i < KT * 64; i += 256) sW[i] = Wt[kt * 64 + i];
        // x tile: float4 loads
        for (int i = tid; i < 64 * (KT / 4); i += 256) {
            int r = i / (KT / 4), kq = i % (KT / 4);
            int row = row0 + r;
            float4 v = make_float4(0.f, 0.f, 0.f, 0.f);
            if (row < NN) {
                v = *reinterpret_cast<const float4*>(&x[(long)row * K + kt + kq * 4]);
                if (RELU) {
                    v.x = fmaxf(v.x, 0.f); v.y = fmaxf(v.y, 0.f);
                    v.z = fmaxf(v.z, 0.f); v.w = fmaxf(v.w, 0.f);
                }
            }
            *reinterpret_cast<float4*>(&sx[r * KTP + kq * 4]) = v;
        }
        __syncthreads();

        const float* xb = &sx[(ty * 4) * KTP];
#pragma unroll
        for (int k = 0; k < KT; k += 4) {
            float a0[4], a1[4], a2[4], a3[4];
            *reinterpret_cast<float4*>(a0) = *reinterpret_cast<const float4*>(&xb[k]);
            *reinterpret_cast<float4*>(a1) = *reinterpret_cast<const float4*>(&xb[KTP + k]);
            *reinterpret_cast<float4*>(a2) = *reinterpret_cast<const float4*>(&xb[2 * KTP + k]);
            *reinterpret_cast<float4*>(a3) = *reinterpret_cast<const float4*>(&xb[3 * KTP + k]);
#pragma unroll
            for (int kk = 0; kk < 4; kk++) {
                float4 b = *reinterpret_cast<const float4*>(&sW[(k + kk) * 64 + tx * 4]);
                acc[0][0] = fmaf(a0[kk], b.x, acc[0][0]);
                acc[0][1] = fmaf(a0[kk], b.y, acc[0][1]);
                acc[0][2] = fmaf(a0[kk], b.z, acc[0][2]);
                acc[0][3] = fmaf(a0[kk], b.w, acc[0][3]);
                acc[1][0] = fmaf(a1[kk], b.x, acc[1][0]);
                acc[1][1] = fmaf(a1[kk], b.y, acc[1][1]);
                acc[1][2] = fmaf(a1[kk], b.z, acc[1][2]);
                acc[1][3] = fmaf(a1[kk], b.w, acc[1][3]);
                acc[2][0] = fmaf(a2[kk], b.x, acc[2][0]);
                acc[2][1] = fmaf(a2[kk], b.y, acc[2][1]);
                acc[2][2] = fmaf(a2[kk], b.z, acc[2][2]);
                acc[2][3] = fmaf(a2[kk], b.w, acc[2][3]);
                acc[3][0] = fmaf(a3[kk], b.x, acc[3][0]);
                acc[3][1] = fmaf(a3[kk], b.y, acc[3][1]);
                acc[3][2] = fmaf(a3[kk], b.z, acc[3][2]);
                acc[3][3] = fmaf(a3[kk], b.w, acc[3][3]);
            }
        }
        __syncthreads();
    }

    // Epilogue: store h, reduce alpha dot products over the 16 col-lanes
    float c0 = asrc[tx * 4 + 0], c1 = asrc[tx * 4 + 1], c2 = asrc[tx * 4 + 2], c3 = asrc[tx * 4 + 3];
    float d0 = adst[tx * 4 + 0], d1 = adst[tx * 4 + 1], d2 = adst[tx * 4 + 2], d3 = adst[tx * 4 + 3];

    float sA[4], sD[4];
#pragma unroll
    for (int i = 0; i < 4; i++) {
        int row = row0 + ty * 4 + i;
        float4 v = make_float4(acc[i][0], acc[i][1], acc[i][2], acc[i][3]);
        if (row < NN)
            *reinterpret_cast<float4*>(&h[(long)row * HD + tx * 4]) = v;
        sA[i] = v.x * c0 + v.y * c1 + v.z * c2 + v.w * c3;
        sD[i] = v.x * d0 + v.y * d1 + v.z * d2 + v.w * d3;
    }
#pragma unroll
    for (int off = 8; off >= 1; off >>= 1) {
#pragma unroll
        for (int i = 0; i < 4; i++) {
            sA[i] += __shfl_xor_sync(0xffffffffu, sA[i], off);
            sD[i] += __shfl_xor_sync(0xffffffffu, sD[i], off);
        }
    }
    if (tx == 0) {
#pragma unroll
        for (int i = 0; i < 4; i++) {
            int row = row0 + ty * 4 + i;
            if (row < NN) { out_as[row] = sA[i]; out_ad[row] = sD[i]; }
        }
    }
}

// ---------------- node kernel: softmax + aggregate, warp per dst node -------
__global__ void node_kernel(const float* __restrict__ h, const float* __restrict__ as_,
                            const float* __restrict__ ad_, const float* __restrict__ bias,
                            float* __restrict__ outp)
{
    int node = (blockIdx.x * blockDim.x + threadIdx.x) >> 5;
    int lane = threadIdx.x & 31;
    if (node >= NN) return;

    int beg = g_off[node], end = g_off[node + 1];
    float adv = __ldg(&ad_[node]);

    // pass 1: segment max (lanes stride edges)
    float m = -3.4e38f;
    for (int j = beg + lane; j < end; j += 32) {
        float e = __ldg(&as_[g_csrc[j]]) + adv;
        e = e > 0.f ? e : 0.2f * e;
        m = fmaxf(m, e);
    }
#pragma unroll
    for (int o = 16; o >= 1; o >>= 1) m = fmaxf(m, __shfl_xor_sync(0xffffffffu, m, o));

    // pass 2: exp weights + weighted gather-accumulate (2 channels / lane)
    float den = 0.f, accx = 0.f, accy = 0.f;
    for (int base = beg; base < end; base += 32) {
        int j = base + lane;
        int s = 0; float ex = 0.f;
        if (j < end) {
            s = g_csrc[j];
            float e = __ldg(&as_[s]) + adv;
            e = e > 0.f ? e : 0.2f * e;
            ex = __expf(e - m);
            den += ex;
        }
        int cnt = min(32, end - base);
        for (int t = 0; t < cnt; t++) {
            int   ss = __shfl_sync(0xffffffffu, s, t);
            float ee = __shfl_sync(0xffffffffu, ex, t);
            float2 hv = *reinterpret_cast<const float2*>(&h[(long)ss * HD + lane * 2]);
            accx = fmaf(ee, hv.x, accx);
            accy = fmaf(ee, hv.y, accy);
        }
    }
#pragma unroll
    for (int o = 16; o >= 1; o >>= 1) den += __shfl_xor_sync(0xffffffffu, den, o);

    float inv = 1.f / den;
    float2 b = *reinterpret_cast<const float2*>(&bias[lane * 2]);
    float2 o2 = make_float2(fmaf(accx, inv, b.x), fmaf(accy, inv, b.y));
    *reinterpret_cast<float2*>(&outp[(long)node * HD + lane * 2]) = o2;
}

// ---------------- launch -----------------------------------------------------
extern "C" void kernel_launch(void* const* d_in, const int* in_sizes, int n_in,
                              void* d_out, int out_size)
{
    const float* x   = (const float*)d_in[0];
    const void*  ei  = d_in[1];
    const float* W1  = (const float*)d_in[2];
    const float* a1s = (const float*)d_in[3];
    const float* a1d = (const float*)d_in[4];
    const float* b1  = (const float*)d_in[5];
    const float* W2  = (const float*)d_in[6];
    const float* a2s = (const float*)d_in[7];
    const float* a2d = (const float*)d_in[8];
    const float* b2  = (const float*)d_in[9];
    float* out = (float*)d_out;

    float *p_h, *p_agg1, *p_as, *p_ad, *p_wt1, *p_wt2;
    cudaGetSymbolAddress((void**)&p_h,    g_h);
    cudaGetSymbolAddress((void**)&p_agg1, g_agg1);
    cudaGetSymbolAddress((void**)&p_as,   g_as);
    cudaGetSymbolAddress((void**)&p_ad,   g_ad);
    cudaGetSymbolAddress((void**)&p_wt1,  g_Wt1);
    cudaGetSymbolAddress((void**)&p_wt2,  g_Wt2);

    const int TB = 256;
    const int GB_E    = (ETOT + TB - 1) / TB;
    const int GB_N    = (NN + TB - 1) / TB;
    const int GB_GEMM = (NN + 63) / 64;
    const int GB_NODE = (NN * 32 + TB - 1) / TB;

    // ---- one-time graph prep (runs every call; same result) ----
    zero_kernel<<<GB_N, TB>>>();
    detect_kernel<<<1, 256>>>((const unsigned*)ei);
    decode_kernel<<<GB_E, TB>>>(ei);          // also builds degree histogram
    scanA_kernel<<<NBLK, 1024>>>();
    scanB_kernel<<<1, 32>>>();
    scanC_kernel<<<NBLK, 1024>>>();
    scatter_kernel<<<GB_E, TB>>>();
    wtr_kernel<<<(128 * 64 + TB - 1) / TB, TB>>>(W1, W2);

    // ---- layer 1 ----
    gemm_kernel<128, false><<<GB_GEMM, TB>>>(x, p_wt1, a1s, a1d, p_h, p_as, p_ad);
    node_kernel<<<GB_NODE, TB>>>(p_h, p_as, p_ad, b1, p_agg1);

    // ---- layer 2 ----
    gemm_kernel<64, true><<<GB_GEMM, TB>>>(p_agg1, p_wt2, a2s, a2d, p_h, p_as, p_ad);
    node_kernel<<<GB_NODE, TB>>>(p_h, p_as, p_ad, b2, out);
}

// round 6
// speedup vs baseline: 1.8743x; 1.2863x over previous
#include <cuda_runtime.h>
#include <cuda_bf16.h>

// Problem constants
#define NN   50000
#define EE   800000
#define ETOT 850000   // EE + NN self loops
#define HD   64
#define NBLK 49       // ceil(NN / 1024)

// ---------------- scratch (static device globals; no allocation) ------------
static __device__ int   g_csrc[ETOT];     // CSR-ordered src indices
static __device__ int   g_deg[NN];
static __device__ int   g_off[NN + 1];
static __device__ int   g_cur[NN];
static __device__ int   g_part[64];
static __device__ float g_h[NN * HD];     // transformed features
static __device__ float g_agg1[NN * HD];  // layer-1 output (incl. bias)
static __device__ float g_as[NN];
static __device__ float g_ad[NN];
static __device__ float g_Wt1[128 * 64];  // W1 transposed: [k][c]
static __device__ float g_Wt2[64 * 64];   // W2 transposed
static __device__ int   g_is64;

// ---------------- setup kernels ---------------------------------------------
__global__ void zero_kernel() {
    int i = blockIdx.x * blockDim.x + threadIdx.x;
    if (i < NN) { g_deg[i] = 0; g_cur[i] = 0; }
}

__global__ void detect_kernel(const unsigned* __restrict__ w) {
    __shared__ int s;
    if (threadIdx.x == 0) s = 0;
    __syncthreads();
    // int64 values < 2^31 -> every odd 32-bit word is 0.
    if (w[2 * threadIdx.x + 1] != 0u) atomicOr(&s, 1);
    __syncthreads();
    if (threadIdx.x == 0) g_is64 = (s == 0);
}

// degree histogram: reads only the dst row of edge_index (+ self loops)
__global__ void deg_kernel(const void* __restrict__ ei) {
    int i = blockIdx.x * blockDim.x + threadIdx.x;
    if (i >= ETOT) return;
    int d;
    if (i >= EE) d = i - EE;
    else if (g_is64) d = (int)((const long long*)ei)[EE + i];
    else             d = ((const int*)ei)[EE + i];
    atomicAdd(&g_deg[d], 1);
}

// 3-pass exclusive scan of g_deg -> g_off
__global__ void scanA_kernel() {
    __shared__ int sm[1024];
    int tid = threadIdx.x;
    int i = blockIdx.x * 1024 + tid;
    int v = (i < NN) ? g_deg[i] : 0;
    sm[tid] = v;
    __syncthreads();
    for (int off = 1; off < 1024; off <<= 1) {
        int t = (tid >= off) ? sm[tid - off] : 0;
        __syncthreads();
        sm[tid] += t;
        __syncthreads();
    }
    if (i < NN) g_off[i + 1] = sm[tid];
    if (tid == 1023) g_part[blockIdx.x] = sm[1023];
}
__global__ void scanB_kernel() {
    if (threadIdx.x == 0) {
        int acc = 0;
        for (int b = 0; b < NBLK; b++) { int t = g_part[b]; g_part[b] = acc; acc += t; }
    }
}
__global__ void scanC_kernel() {
    int i = blockIdx.x * 1024 + threadIdx.x;
    if (i < NN) g_off[i + 1] += g_part[blockIdx.x];
    if (i == 0) g_off[0] = 0;
}

// scatter src indices into CSR order (re-decodes edge list directly)
__global__ void scatter_kernel(const void* __restrict__ ei) {
    int i = blockIdx.x * blockDim.x + threadIdx.x;
    if (i >= ETOT) return;
    int s, d;
    if (i >= EE) { s = i - EE; d = s; }
    else if (g_is64) {
        const long long* p = (const long long*)ei;
        s = (int)p[i]; d = (int)p[EE + i];
    } else {
        const int* p = (const int*)ei;
        s = p[i]; d = p[EE + i];
    }
    int pos = g_off[d] + atomicAdd(&g_cur[d], 1);
    g_csrc[pos] = s;
}

// one-time weight transpose: Wt[k][c] = W[c][k]
__global__ void wtr_kernel(const float* __restrict__ W1, const float* __restrict__ W2) {
    int i = blockIdx.x * blockDim.x + threadIdx.x;
    if (i < 128 * 64) { int k = i % 128, c = i / 128; g_Wt1[k * 64 + c] = W1[c * 128 + k]; }
    if (i < 64 * 64)  { int k = i % 64,  c = i / 64;  g_Wt2[k * 64 + c] = W2[c * 64 + k]; }
}

// ---------------- GEMM: h = x @ W^T, fused alpha epilogue -------------------
template <int K, bool RELU>
__global__ void gemm_kernel(const float* __restrict__ x, const float* __restrict__ Wt,
                            const float* __restrict__ asrc, const float* __restrict__ adst,
                            float* __restrict__ h, float* __restrict__ out_as,
                            float* __restrict__ out_ad)
{
    constexpr int KT = 64;
    constexpr int KTP = KT + 4;
    __shared__ float sW[KT * 64];
    __shared__ float sx[64 * KTP];

    int tid  = threadIdx.x;
    int row0 = blockIdx.x * 64;
    int tx = tid & 15;
    int ty = tid >> 4;

    float acc[4][4];
#pragma unroll
    for (int i = 0; i < 4; i++)
#pragma unroll
        for (int j = 0; j < 4; j++) acc[i][j] = 0.f;

    for (int kt = 0; kt < K; kt += KT) {
        for (int i = tid; i < KT * 64; i += 256) sW[i] = Wt[kt * 64 + i];
        for (int i = tid; i < 64 * (KT / 4); i += 256) {
            int r = i / (KT / 4), kq = i % (KT / 4);
            int row = row0 + r;
            float4 v = make_float4(0.f, 0.f, 0.f, 0.f);
            if (row < NN) {
                v = *reinterpret_cast<const float4*>(&x[(long)row * K + kt + kq * 4]);
                if (RELU) {
                    v.x = fmaxf(v.x, 0.f); v.y = fmaxf(v.y, 0.f);
                    v.z = fmaxf(v.z, 0.f); v.w = fmaxf(v.w, 0.f);
                }
            }
            *reinterpret_cast<float4*>(&sx[r * KTP + kq * 4]) = v;
        }
        __syncthreads();

        const float* xb = &sx[(ty * 4) * KTP];
#pragma unroll
        for (int k = 0; k < KT; k += 4) {
            float a0[4], a1[4], a2[4], a3[4];
            *reinterpret_cast<float4*>(a0) = *reinterpret_cast<const float4*>(&xb[k]);
            *reinterpret_cast<float4*>(a1) = *reinterpret_cast<const float4*>(&xb[KTP + k]);
            *reinterpret_cast<float4*>(a2) = *reinterpret_cast<const float4*>(&xb[2 * KTP + k]);
            *reinterpret_cast<float4*>(a3) = *reinterpret_cast<const float4*>(&xb[3 * KTP + k]);
#pragma unroll
            for (int kk = 0; kk < 4; kk++) {
                float4 b = *reinterpret_cast<const float4*>(&sW[(k + kk) * 64 + tx * 4]);
                acc[0][0] = fmaf(a0[kk], b.x, acc[0][0]);
                acc[0][1] = fmaf(a0[kk], b.y, acc[0][1]);
                acc[0][2] = fmaf(a0[kk], b.z, acc[0][2]);
                acc[0][3] = fmaf(a0[kk], b.w, acc[0][3]);
                acc[1][0] = fmaf(a1[kk], b.x, acc[1][0]);
                acc[1][1] = fmaf(a1[kk], b.y, acc[1][1]);
                acc[1][2] = fmaf(a1[kk], b.z, acc[1][2]);
                acc[1][3] = fmaf(a1[kk], b.w, acc[1][3]);
                acc[2][0] = fmaf(a2[kk], b.x, acc[2][0]);
                acc[2][1] = fmaf(a2[kk], b.y, acc[2][1]);
                acc[2][2] = fmaf(a2[kk], b.z, acc[2][2]);
                acc[2][3] = fmaf(a2[kk], b.w, acc[2][3]);
                acc[3][0] = fmaf(a3[kk], b.x, acc[3][0]);
                acc[3][1] = fmaf(a3[kk], b.y, acc[3][1]);
                acc[3][2] = fmaf(a3[kk], b.z, acc[3][2]);
                acc[3][3] = fmaf(a3[kk], b.w, acc[3][3]);
            }
        }
        __syncthreads();
    }

    float c0 = asrc[tx * 4 + 0], c1 = asrc[tx * 4 + 1], c2 = asrc[tx * 4 + 2], c3 = asrc[tx * 4 + 3];
    float d0 = adst[tx * 4 + 0], d1 = adst[tx * 4 + 1], d2 = adst[tx * 4 + 2], d3 = adst[tx * 4 + 3];

    float sA[4], sD[4];
#pragma unroll
    for (int i = 0; i < 4; i++) {
        int row = row0 + ty * 4 + i;
        float4 v = make_float4(acc[i][0], acc[i][1], acc[i][2], acc[i][3]);
        if (row < NN)
            *reinterpret_cast<float4*>(&h[(long)row * HD + tx * 4]) = v;
        sA[i] = v.x * c0 + v.y * c1 + v.z * c2 + v.w * c3;
        sD[i] = v.x * d0 + v.y * d1 + v.z * d2 + v.w * d3;
    }
#pragma unroll
    for (int off = 8; off >= 1; off >>= 1) {
#pragma unroll
        for (int i = 0; i < 4; i++) {
            sA[i] += __shfl_xor_sync(0xffffffffu, sA[i], off);
            sD[i] += __shfl_xor_sync(0xffffffffu, sD[i], off);
        }
    }
    if (tx == 0) {
#pragma unroll
        for (int i = 0; i < 4; i++) {
            int row = row0 + ty * 4 + i;
            if (row < NN) { out_as[row] = sA[i]; out_ad[row] = sD[i]; }
        }
    }
}

// ---------------- node kernel: single-sweep softmax-aggregate ---------------
// Softmax shift-invariance: out = sum(exp(e_j) h_j) / sum(exp(e_j)).
// Warp per dst node. Gather layout: 2 edges in flight, 16 lanes x float4 each.
__global__ void node_kernel(const float* __restrict__ h, const float* __restrict__ as_,
                            const float* __restrict__ ad_, const float* __restrict__ bias,
                            float* __restrict__ outp)
{
    int node = (blockIdx.x * blockDim.x + threadIdx.x) >> 5;
    int lane = threadIdx.x & 31;
    if (node >= NN) return;

    int beg = g_off[node], end = g_off[node + 1];
    float adv = __ldg(&ad_[node]);

    int  half = lane >> 4;     // 0: even edge, 1: odd edge
    int  ch   = lane & 15;     // channel group: 4 floats at ch*4

    float den = 0.f;
    float4 acc = make_float4(0.f, 0.f, 0.f, 0.f);

    for (int base = beg; base < end; base += 32) {
        int j = base + lane;
        int s = 0; float ex = 0.f;
        if (j < end) {
            s = g_csrc[j];
            float e = __ldg(&as_[s]) + adv;
            e = e > 0.f ? e : 0.2f * e;
            ex = __expf(e);
            den += ex;
        }
        int cnt = min(32, end - base);
        for (int t = 0; t < cnt; t += 2) {
            int tt = t + half;
            int   ss = __shfl_sync(0xffffffffu, s, tt & 31);
            float ee = __shfl_sync(0xffffffffu, ex, tt & 31);
            if (tt < cnt) {
                float4 hv = *reinterpret_cast<const float4*>(&h[(long)ss * HD + ch * 4]);
                acc.x = fmaf(ee, hv.x, acc.x);
                acc.y = fmaf(ee, hv.y, acc.y);
                acc.z = fmaf(ee, hv.z, acc.z);
                acc.w = fmaf(ee, hv.w, acc.w);
            }
        }
    }
    // reduce den across warp; combine the two edge-halves of acc
#pragma unroll
    for (int o = 16; o >= 1; o >>= 1) den += __shfl_xor_sync(0xffffffffu, den, o);
    acc.x += __shfl_xor_sync(0xffffffffu, acc.x, 16);
    acc.y += __shfl_xor_sync(0xffffffffu, acc.y, 16);
    acc.z += __shfl_xor_sync(0xffffffffu, acc.z, 16);
    acc.w += __shfl_xor_sync(0xffffffffu, acc.w, 16);

    if (half == 0) {
        float inv = 1.f / den;
        float4 b = *reinterpret_cast<const float4*>(&bias[ch * 4]);
        float4 o4 = make_float4(fmaf(acc.x, inv, b.x), fmaf(acc.y, inv, b.y),
                                fmaf(acc.z, inv, b.z), fmaf(acc.w, inv, b.w));
        *reinterpret_cast<float4*>(&outp[(long)node * HD + ch * 4]) = o4;
    }
}

// ---------------- launch -----------------------------------------------------
extern "C" void kernel_launch(void* const* d_in, const int* in_sizes, int n_in,
                              void* d_out, int out_size)
{
    const float* x   = (const float*)d_in[0];
    const void*  ei  = d_in[1];
    const float* W1  = (const float*)d_in[2];
    const float* a1s = (const float*)d_in[3];
    const float* a1d = (const float*)d_in[4];
    const float* b1  = (const float*)d_in[5];
    const float* W2  = (const float*)d_in[6];
    const float* a2s = (const float*)d_in[7];
    const float* a2d = (const float*)d_in[8];
    const float* b2  = (const float*)d_in[9];
    float* out = (float*)d_out;

    float *p_h, *p_agg1, *p_as, *p_ad, *p_wt1, *p_wt2;
    cudaGetSymbolAddress((void**)&p_h,    g_h);
    cudaGetSymbolAddress((void**)&p_agg1, g_agg1);
    cudaGetSymbolAddress((void**)&p_as,   g_as);
    cudaGetSymbolAddress((void**)&p_ad,   g_ad);
    cudaGetSymbolAddress((void**)&p_wt1,  g_Wt1);
    cudaGetSymbolAddress((void**)&p_wt2,  g_Wt2);

    const int TB = 256;
    const int GB_E    = (ETOT + TB - 1) / TB;
    const int GB_N    = (NN + TB - 1) / TB;
    const int GB_GEMM = (NN + 63) / 64;
    const int GB_NODE = (NN * 32 + TB - 1) / TB;

    // ---- graph prep ----
    zero_kernel<<<GB_N, TB>>>();
    detect_kernel<<<1, 256>>>((const unsigned*)ei);
    deg_kernel<<<GB_E, TB>>>(ei);
    scanA_kernel<<<NBLK, 1024>>>();
    scanB_kernel<<<1, 32>>>();
    scanC_kernel<<<NBLK, 1024>>>();
    scatter_kernel<<<GB_E, TB>>>(ei);
    wtr_kernel<<<(128 * 64 + TB - 1) / TB, TB>>>(W1, W2);

    // ---- layer 1 ----
    gemm_kernel<128, false><<<GB_GEMM, TB>>>(x, p_wt1, a1s, a1d, p_h, p_as, p_ad);
    node_kernel<<<GB_NODE, TB>>>(p_h, p_as, p_ad, b1, p_agg1);

    // ---- layer 2 ----
    gemm_kernel<64, true><<<GB_GEMM, TB>>>(p_agg1, p_wt2, a2s, a2d, p_h, p_as, p_ad);
    node_kernel<<<GB_NODE, TB>>>(p_h, p_as, p_ad, b2, out);
}

// round 9
// speedup vs baseline: 2.0077x; 1.0712x over previous
#include <cuda_runtime.h>
#include <cuda_fp16.h>

// Problem constants
#define NN   50000
#define EE   800000
#define ETOT 850000   // EE + NN self loops
#define HD   64
#define NBLK 49       // ceil(NN / 1024)

// ---------------- scratch (static device globals; no allocation) ------------
static __device__ int    g_csrc[ETOT];     // CSR-ordered src indices
static __device__ int    g_deg[NN];
static __device__ int    g_off[NN + 1];
static __device__ int    g_cur[NN];
static __device__ int    g_part[64];
static __device__ __half g_hh[NN * HD];    // transformed features (fp16, gather operand)
static __device__ float  g_agg1[NN * HD];  // layer-1 output (incl. bias), fp32
static __device__ float  g_as[NN];
static __device__ float  g_ad[NN];
static __device__ float  g_Wt1[128 * 64];  // W1 transposed: [k][c]
static __device__ float  g_Wt2[64 * 64];   // W2 transposed
static __device__ int    g_is64;

// ---------------- setup kernels ---------------------------------------------
// zero deg/cur + transpose both weight matrices in one launch
__global__ void setup_kernel(const float* __restrict__ W1, const float* __restrict__ W2) {
    int i = blockIdx.x * blockDim.x + threadIdx.x;
    if (i < NN) { g_deg[i] = 0; g_cur[i] = 0; }
    if (i < 128 * 64) { int k = i % 128, c = i / 128; g_Wt1[k * 64 + c] = W1[c * 128 + k]; }
    if (i < 64 * 64)  { int k = i % 64,  c = i / 64;  g_Wt2[k * 64 + c] = W2[c * 64 + k]; }
}

__global__ void detect_kernel(const unsigned* __restrict__ w) {
    __shared__ int s;
    if (threadIdx.x == 0) s = 0;
    __syncthreads();
    // int64 values < 2^31 -> every odd 32-bit word is 0.
    if (w[2 * threadIdx.x + 1] != 0u) atomicOr(&s, 1);
    __syncthreads();
    if (threadIdx.x == 0) g_is64 = (s == 0);
}

// degree histogram: reads only the dst row of edge_index (+ self loops)
__global__ void deg_kernel(const void* __restrict__ ei) {
    int i = blockIdx.x * blockDim.x + threadIdx.x;
    if (i >= ETOT) return;
    int d;
    if (i >= EE) d = i - EE;
    else if (g_is64) d = (int)((const long long*)ei)[EE + i];
    else             d = ((const int*)ei)[EE + i];
    atomicAdd(&g_deg[d], 1);
}

// warp-shuffle block scan (inclusive) -> g_off[i+1], block sums -> g_part
__global__ void scanA_kernel() {
    __shared__ int wsum[32];
    int tid = threadIdx.x;
    int i = blockIdx.x * 1024 + tid;
    int x = (i < NN) ? g_deg[i] : 0;
#pragma unroll
    for (int o = 1; o < 32; o <<= 1) {
        int t = __shfl_up_sync(0xffffffffu, x, o);
        if ((tid & 31) >= o) x += t;
    }
    if ((tid & 31) == 31) wsum[tid >> 5] = x;
    __syncthreads();
    if (tid < 32) {
        int w = wsum[tid];
#pragma unroll
        for (int o = 1; o < 32; o <<= 1) {
            int t = __shfl_up_sync(0xffffffffu, w, o);
            if (tid >= o) w += t;
        }
        wsum[tid] = w;
    }
    __syncthreads();
    if (tid >= 32) x += wsum[(tid >> 5) - 1];
    if (i < NN) g_off[i + 1] = x;
    if (tid == 1023) g_part[blockIdx.x] = x;
}
__global__ void scanB_kernel() {
    if (threadIdx.x == 0) {
        int acc = 0;
        for (int b = 0; b < NBLK; b++) { int t = g_part[b]; g_part[b] = acc; acc += t; }
    }
}
__global__ void scanC_kernel() {
    int i = blockIdx.x * 1024 + threadIdx.x;
    if (i < NN) g_off[i + 1] += g_part[blockIdx.x];
    if (i == 0) g_off[0] = 0;
}

// scatter src indices into CSR order (re-decodes edge list directly)
__global__ void scatter_kernel(const void* __restrict__ ei) {
    int i = blockIdx.x * blockDim.x + threadIdx.x;
    if (i >= ETOT) return;
    int s, d;
    if (i >= EE) { s = i - EE; d = s; }
    else if (g_is64) {
        const long long* p = (const long long*)ei;
        s = (int)p[i]; d = (int)p[EE + i];
    } else {
        const int* p = (const int*)ei;
        s = p[i]; d = p[EE + i];
    }
    int pos = g_off[d] + atomicAdd(&g_cur[d], 1);
    g_csrc[pos] = s;
}

// ---------------- GEMM: h = x @ W^T (fp16 out), fused alpha epilogue --------
template <int K, bool RELU>
__global__ void gemm_kernel(const float* __restrict__ x, const float* __restrict__ Wt,
                            const float* __restrict__ asrc, const float* __restrict__ adst,
                            __half* __restrict__ h, float* __restrict__ out_as,
                            float* __restrict__ out_ad)
{
    constexpr int KT = 64;
    constexpr int KTP = KT + 4;
    __shared__ float sW[KT * 64];
    __shared__ float sx[64 * KTP];

    int tid  = threadIdx.x;
    int row0 = blockIdx.x * 64;
    int tx = tid & 15;
    int ty = tid >> 4;

    float acc[4][4];
#pragma unroll
    for (int i = 0; i < 4; i++)
#pragma unroll
        for (int j = 0; j < 4; j++) acc[i][j] = 0.f;

    for (int kt = 0; kt < K; kt += KT) {
        for (int i = tid; i < KT * 64; i += 256) sW[i] = Wt[kt * 64 + i];
        for (int i = tid; i < 64 * (KT / 4); i += 256) {
            int r = i / (KT / 4), kq = i % (KT / 4);
            int row = row0 + r;
            float4 v = make_float4(0.f, 0.f, 0.f, 0.f);
            if (row < NN) {
                v = *reinterpret_cast<const float4*>(&x[(long)row * K + kt + kq * 4]);
                if (RELU) {
                    v.x = fmaxf(v.x, 0.f); v.y = fmaxf(v.y, 0.f);
                    v.z = fmaxf(v.z, 0.f); v.w = fmaxf(v.w, 0.f);
                }
            }
            *reinterpret_cast<float4*>(&sx[r * KTP + kq * 4]) = v;
        }
        __syncthreads();

        const float* xb = &sx[(ty * 4) * KTP];
#pragma unroll
        for (int k = 0; k < KT; k += 4) {
            float a0[4], a1[4], a2[4], a3[4];
            *reinterpret_cast<float4*>(a0) = *reinterpret_cast<const float4*>(&xb[k]);
            *reinterpret_cast<float4*>(a1) = *reinterpret_cast<const float4*>(&xb[KTP + k]);
            *reinterpret_cast<float4*>(a2) = *reinterpret_cast<const float4*>(&xb[2 * KTP + k]);
            *reinterpret_cast<float4*>(a3) = *reinterpret_cast<const float4*>(&xb[3 * KTP + k]);
#pragma unroll
            for (int kk = 0; kk < 4; kk++) {
                float4 b = *reinterpret_cast<const float4*>(&sW[(k + kk) * 64 + tx * 4]);
                acc[0][0] = fmaf(a0[kk], b.x, acc[0][0]);
                acc[0][1] = fmaf(a0[kk], b.y, acc[0][1]);
                acc[0][2] = fmaf(a0[kk], b.z, acc[0][2]);
                acc[0][3] = fmaf(a0[kk], b.w, acc[0][3]);
                acc[1][0] = fmaf(a1[kk], b.x, acc[1][0]);
                acc[1][1] = fmaf(a1[kk], b.y, acc[1][1]);
                acc[1][2] = fmaf(a1[kk], b.z, acc[1][2]);
                acc[1][3] = fmaf(a1[kk], b.w, acc[1][3]);
                acc[2][0] = fmaf(a2[kk], b.x, acc[2][0]);
                acc[2][1] = fmaf(a2[kk], b.y, acc[2][1]);
                acc[2][2] = fmaf(a2[kk], b.z, acc[2][2]);
                acc[2][3] = fmaf(a2[kk], b.w, acc[2][3]);
                acc[3][0] = fmaf(a3[kk], b.x, acc[3][0]);
                acc[3][1] = fmaf(a3[kk], b.y, acc[3][1]);
                acc[3][2] = fmaf(a3[kk], b.z, acc[3][2]);
                acc[3][3] = fmaf(a3[kk], b.w, acc[3][3]);
            }
        }
        __syncthreads();
    }

    float c0 = asrc[tx * 4 + 0], c1 = asrc[tx * 4 + 1], c2 = asrc[tx * 4 + 2], c3 = asrc[tx * 4 + 3];
    float d0 = adst[tx * 4 + 0], d1 = adst[tx * 4 + 1], d2 = adst[tx * 4 + 2], d3 = adst[tx * 4 + 3];

    float sA[4], sD[4];
#pragma unroll
    for (int i = 0; i < 4; i++) {
        int row = row0 + ty * 4 + i;
        float4 v = make_float4(acc[i][0], acc[i][1], acc[i][2], acc[i][3]);
        if (row < NN) {
            // convert to fp16 and store 8 bytes (4 halves) via bit-reinterpret
            __half2 pk2[2];
            pk2[0] = __floats2half2_rn(v.x, v.y);
            pk2[1] = __floats2half2_rn(v.z, v.w);
            reinterpret_cast<uint2*>(h)[(long)row * 16 + tx] =
                *reinterpret_cast<const uint2*>(pk2);
        }
        sA[i] = v.x * c0 + v.y * c1 + v.z * c2 + v.w * c3;
        sD[i] = v.x * d0 + v.y * d1 + v.z * d2 + v.w * d3;
    }
#pragma unroll
    for (int off = 8; off >= 1; off >>= 1) {
#pragma unroll
        for (int i = 0; i < 4; i++) {
            sA[i] += __shfl_xor_sync(0xffffffffu, sA[i], off);
            sD[i] += __shfl_xor_sync(0xffffffffu, sD[i], off);
        }
    }
    if (tx == 0) {
#pragma unroll
        for (int i = 0; i < 4; i++) {
            int row = row0 + ty * 4 + i;
            if (row < NN) { out_as[row] = sA[i]; out_ad[row] = sD[i]; }
        }
    }
}

// ---------------- node kernel: single-sweep softmax-aggregate ---------------
// out = sum(exp(e_j) h_j) / sum(exp(e_j)) + bias  (softmax shift-invariance).
// Warp per dst node; 4 edges in flight, 8 lanes x 16B(=8 halves) per edge.
__global__ void node_kernel(const __half* __restrict__ h, const float* __restrict__ as_,
                            const float* __restrict__ ad_, const float* __restrict__ bias,
                            float* __restrict__ outp)
{
    int node = (blockIdx.x * blockDim.x + threadIdx.x) >> 5;
    int lane = threadIdx.x & 31;
    if (node >= NN) return;

    int beg = g_off[node], end = g_off[node + 1];
    float adv = __ldg(&ad_[node]);

    int quarter = lane >> 3;   // which of 4 in-flight edges
    int ch      = lane & 7;    // 8 halves at byte offset ch*16

    float den = 0.f;
    float acc[8];
#pragma unroll
    for (int k = 0; k < 8; k++) acc[k] = 0.f;

    for (int base = beg; base < end; base += 32) {
        int j = base + lane;
        int s = 0; float ex = 0.f;
        if (j < end) {
            s = g_csrc[j];
            float e = __ldg(&as_[s]) + adv;
            e = e > 0.f ? e : 0.2f * e;
            ex = __expf(e);
            den += ex;
        }
        int cnt = min(32, end - base);
        for (int t = 0; t < cnt; t += 4) {
            int tt = t + quarter;
            int   ss = __shfl_sync(0xffffffffu, s, tt & 31);
            float ee = __shfl_sync(0xffffffffu, ex, tt & 31);
            if (tt < cnt) {
                float4 raw = *reinterpret_cast<const float4*>(
                    reinterpret_cast<const char*>(h) + (long)ss * 128 + ch * 16);
                const __half2* hp = reinterpret_cast<const __half2*>(&raw);
#pragma unroll
                for (int k = 0; k < 4; k++) {
                    float2 f = __half22float2(hp[k]);
                    acc[2 * k + 0] = fmaf(ee, f.x, acc[2 * k + 0]);
                    acc[2 * k + 1] = fmaf(ee, f.y, acc[2 * k + 1]);
                }
            }
        }
    }
    // reduce den across warp; combine the 4 edge-quarters of acc
#pragma unroll
    for (int o = 16; o >= 1; o >>= 1) den += __shfl_xor_sync(0xffffffffu, den, o);
#pragma unroll
    for (int k = 0; k < 8; k++) {
        acc[k] += __shfl_xor_sync(0xffffffffu, acc[k], 8);
        acc[k] += __shfl_xor_sync(0xffffffffu, acc[k], 16);
    }

    if (quarter == 0) {
        float inv = 1.f / den;
        float4 b0 = *reinterpret_cast<const float4*>(&bias[ch * 8 + 0]);
        float4 b1 = *reinterpret_cast<const float4*>(&bias[ch * 8 + 4]);
        float4 o0 = make_float4(fmaf(acc[0], inv, b0.x), fmaf(acc[1], inv, b0.y),
                                fmaf(acc[2], inv, b0.z), fmaf(acc[3], inv, b0.w));
        float4 o1 = make_float4(fmaf(acc[4], inv, b1.x), fmaf(acc[5], inv, b1.y),
                                fmaf(acc[6], inv, b1.z), fmaf(acc[7], inv, b1.w));
        *reinterpret_cast<float4*>(&outp[(long)node * HD + ch * 8 + 0]) = o0;
        *reinterpret_cast<float4*>(&outp[(long)node * HD + ch * 8 + 4]) = o1;
    }
}

// ---------------- launch -----------------------------------------------------
extern "C" void kernel_launch(void* const* d_in, const int* in_sizes, int n_in,
                              void* d_out, int out_size)
{
    const float* x   = (const float*)d_in[0];
    const void*  ei  = d_in[1];
    const float* W1  = (const float*)d_in[2];
    const float* a1s = (const float*)d_in[3];
    const float* a1d = (const float*)d_in[4];
    const float* b1  = (const float*)d_in[5];
    const float* W2  = (const float*)d_in[6];
    const float* a2s = (const float*)d_in[7];
    const float* a2d = (const float*)d_in[8];
    const float* b2  = (const float*)d_in[9];
    float* out = (float*)d_out;

    __half* p_h;
    float *p_agg1, *p_as, *p_ad, *p_wt1, *p_wt2;
    cudaGetSymbolAddress((void**)&p_h,    g_hh);
    cudaGetSymbolAddress((void**)&p_agg1, g_agg1);
    cudaGetSymbolAddress((void**)&p_as,   g_as);
    cudaGetSymbolAddress((void**)&p_ad,   g_ad);
    cudaGetSymbolAddress((void**)&p_wt1,  g_Wt1);
    cudaGetSymbolAddress((void**)&p_wt2,  g_Wt2);

    const int TB = 256;
    const int GB_E    = (ETOT + TB - 1) / TB;
    const int GB_N    = (NN + TB - 1) / TB;
    const int GB_GEMM = (NN + 63) / 64;
    const int GB_NODE = (NN * 32 + TB - 1) / TB;

    // ---- graph prep ----
    setup_kernel<<<GB_N, TB>>>(W1, W2);
    detect_kernel<<<1, 256>>>((const unsigned*)ei);
    deg_kernel<<<GB_E, TB>>>(ei);
    scanA_kernel<<<NBLK, 1024>>>();
    scanB_kernel<<<1, 32>>>();
    scanC_kernel<<<NBLK, 1024>>>();
    scatter_kernel<<<GB_E, TB>>>(ei);

    // ---- layer 1 ----
    gemm_kernel<128, false><<<GB_GEMM, TB>>>(x, p_wt1, a1s, a1d, p_h, p_as, p_ad);
    node_kernel<<<GB_NODE, TB>>>(p_h, p_as, p_ad, b1, p_agg1);

    // ---- layer 2 ----
    gemm_kernel<64, true><<<GB_GEMM, TB>>>(p_agg1, p_wt2, a2s, a2d, p_h, p_as, p_ad);
    node_kernel<<<GB_NODE, TB>>>(p_h, p_as, p_ad, b2, out);
}

// round 12
// speedup vs baseline: 2.0718x; 1.0319x over previous
#include <cuda_runtime.h>
#include <cuda_fp16.h>
#include <mma.h>
using namespace nvcuda;

// Problem constants
#define NN   50000
#define EE   800000
#define ETOT 850000   // EE + NN self loops
#define HD   64
#define NBLK 49       // ceil(NN / 1024)

// ---------------- scratch (static device globals; no allocation) ------------
static __device__ int    g_csrc[ETOT];     // CSR-ordered src indices
static __device__ int    g_deg[NN];
static __device__ int    g_off[NN + 1];
static __device__ int    g_cur[NN];
static __device__ int    g_part[64];
static __device__ __half g_hh[NN * HD];    // transformed features (fp16, gather operand)
static __device__ float  g_agg1[NN * HD];  // layer-1 output (incl. bias), fp32
static __device__ float  g_as[NN];
static __device__ float  g_ad[NN];
static __device__ __half g_Wth1[128 * 64]; // W1^T in fp16: [k][c]
static __device__ __half g_Wth2[64 * 64];  // W2^T in fp16
static __device__ int    g_is64;

// ---------------- setup: zero counters + transpose/convert weights ----------
__global__ void setup_kernel(const float* __restrict__ W1, const float* __restrict__ W2) {
    int i = blockIdx.x * blockDim.x + threadIdx.x;
    if (i < NN) { g_deg[i] = 0; g_cur[i] = 0; }
    if (i < 128 * 64) { int k = i % 128, c = i / 128; g_Wth1[k * 64 + c] = __float2half(W1[c * 128 + k]); }
    if (i < 64 * 64)  { int k = i % 64,  c = i / 64;  g_Wth2[k * 64 + c] = __float2half(W2[c * 64 + k]); }
}

__global__ void detect_kernel(const unsigned* __restrict__ w) {
    __shared__ int s;
    if (threadIdx.x == 0) s = 0;
    __syncthreads();
    // int64 values < 2^31 -> every odd 32-bit word is 0.
    if (w[2 * threadIdx.x + 1] != 0u) atomicOr(&s, 1);
    __syncthreads();
    if (threadIdx.x == 0) g_is64 = (s == 0);
}

// degree histogram: reads only the dst row of edge_index (+ self loops)
__global__ void deg_kernel(const void* __restrict__ ei) {
    int i = blockIdx.x * blockDim.x + threadIdx.x;
    if (i >= ETOT) return;
    int d;
    if (i >= EE) d = i - EE;
    else if (g_is64) d = (int)((const long long*)ei)[EE + i];
    else             d = ((const int*)ei)[EE + i];
    atomicAdd(&g_deg[d], 1);
}

// warp-shuffle block scan (inclusive) -> g_off[i+1], block sums -> g_part
__global__ void scanA_kernel() {
    __shared__ int wsum[32];
    int tid = threadIdx.x;
    int i = blockIdx.x * 1024 + tid;
    int x = (i < NN) ? g_deg[i] : 0;
#pragma unroll
    for (int o = 1; o < 32; o <<= 1) {
        int t = __shfl_up_sync(0xffffffffu, x, o);
        if ((tid & 31) >= o) x += t;
    }
    if ((tid & 31) == 31) wsum[tid >> 5] = x;
    __syncthreads();
    if (tid < 32) {
        int w = wsum[tid];
#pragma unroll
        for (int o = 1; o < 32; o <<= 1) {
            int t = __shfl_up_sync(0xffffffffu, w, o);
            if (tid >= o) w += t;
        }
        wsum[tid] = w;
    }
    __syncthreads();
    if (tid >= 32) x += wsum[(tid >> 5) - 1];
    if (i < NN) g_off[i + 1] = x;
    if (tid == 1023) g_part[blockIdx.x] = x;
}
__global__ void scanB_kernel() {
    if (threadIdx.x == 0) {
        int acc = 0;
        for (int b = 0; b < NBLK; b++) { int t = g_part[b]; g_part[b] = acc; acc += t; }
    }
}
__global__ void scanC_kernel() {
    int i = blockIdx.x * 1024 + threadIdx.x;
    if (i < NN) g_off[i + 1] += g_part[blockIdx.x];
    if (i == 0) g_off[0] = 0;
}

// scatter src indices into CSR order (re-decodes edge list directly)
__global__ void scatter_kernel(const void* __restrict__ ei) {
    int i = blockIdx.x * blockDim.x + threadIdx.x;
    if (i >= ETOT) return;
    int s, d;
    if (i >= EE) { s = i - EE; d = s; }
    else if (g_is64) {
        const long long* p = (const long long*)ei;
        s = (int)p[i]; d = (int)p[EE + i];
    } else {
        const int* p = (const int*)ei;
        s = p[i]; d = p[EE + i];
    }
    int pos = g_off[d] + atomicAdd(&g_cur[d], 1);
    g_csrc[pos] = s;
}

// ---------------- WMMA GEMM: h = x @ W^T (fp16 in/out, fp32 accum) ----------
// 64 rows / block of 128 threads (4 warps). Warp w computes rows 16w..16w+15
// against all 64 output cols via 4 accumulator fragments. Fused epilogue
// computes as/ad dot products from the fp32 accumulators.
template <int K, bool RELU>
__global__ void gemm_kernel(const float* __restrict__ x, const __half* __restrict__ Wth,
                            const float* __restrict__ asrc, const float* __restrict__ adst,
                            __half* __restrict__ h, float* __restrict__ out_as,
                            float* __restrict__ out_ad)
{
    __shared__ __align__(16) __half sW[K * 64];                 // B tile [K][64]
    __shared__ __align__(16) union SB {
        __half xin[64 * K];      // A tile  [64][K]
        float  out[64 * 64];     // C tile  [64][64]
    } sb;

    int tid  = threadIdx.x;
    int wid  = tid >> 5;
    int row0 = blockIdx.x * 64;

    // load W tile (fp16, coalesced 16B)
    for (int i = tid; i < K * 64 / 8; i += 128)
        reinterpret_cast<uint4*>(sW)[i] = reinterpret_cast<const uint4*>(Wth)[i];

    // load x tile: float4 -> half2 pairs
    for (int i = tid; i < 64 * (K / 4); i += 128) {
        int r = i / (K / 4), kq = i % (K / 4);
        int row = row0 + r;
        float4 v = make_float4(0.f, 0.f, 0.f, 0.f);
        if (row < NN) {
            v = *reinterpret_cast<const float4*>(&x[(long)row * K + kq * 4]);
            if (RELU) {
                v.x = fmaxf(v.x, 0.f); v.y = fmaxf(v.y, 0.f);
                v.z = fmaxf(v.z, 0.f); v.w = fmaxf(v.w, 0.f);
            }
        }
        __half2 p[2];
        p[0] = __floats2half2_rn(v.x, v.y);
        p[1] = __floats2half2_rn(v.z, v.w);
        *reinterpret_cast<uint2*>(&sb.xin[r * K + kq * 4]) = *reinterpret_cast<const uint2*>(p);
    }
    __syncthreads();

    // MMA mainloop
    wmma::fragment<wmma::accumulator, 16, 16, 16, float> acc[4];
#pragma unroll
    for (int n = 0; n < 4; n++) wmma::fill_fragment(acc[n], 0.f);

#pragma unroll
    for (int k = 0; k < K; k += 16) {
        wmma::fragment<wmma::matrix_a, 16, 16, 16, __half, wmma::row_major> af;
        wmma::load_matrix_sync(af, &sb.xin[wid * 16 * K + k], K);
#pragma unroll
        for (int n = 0; n < 4; n++) {
            wmma::fragment<wmma::matrix_b, 16, 16, 16, __half, wmma::row_major> bf;
            wmma::load_matrix_sync(bf, &sW[k * 64 + n * 16], 64);
            wmma::mma_sync(acc[n], af, bf, acc[n]);
        }
    }
    __syncthreads();   // xin no longer needed; reuse as out

#pragma unroll
    for (int n = 0; n < 4; n++)
        wmma::store_matrix_sync(&sb.out[wid * 16 * 64 + n * 16], acc[n], 64, wmma::mem_row_major);
    __syncthreads();

    // Epilogue: 2 threads per row (half each); fp16 h store + alpha dots
    int r  = tid >> 1;
    int hf = tid & 1;
    int grow = row0 + r;

    float sA = 0.f, sD = 0.f;
    __half2 hpk[16];
#pragma unroll
    for (int i = 0; i < 16; i++) {
        int cc = ((r + i) & 15) * 2;          // staggered even column within half
        int c  = hf * 32 + cc;
        float2 v = *reinterpret_cast<const float2*>(&sb.out[r * 64 + c]);
        sA = fmaf(v.x, __ldg(&asrc[c]), fmaf(v.y, __ldg(&asrc[c + 1]), sA));
        sD = fmaf(v.x, __ldg(&adst[c]), fmaf(v.y, __ldg(&adst[c + 1]), sD));
        hpk[cc >> 1] = __floats2half2_rn(v.x, v.y);
    }
    // combine the two halves of each row
    sA += __shfl_xor_sync(0xffffffffu, sA, 1);
    sD += __shfl_xor_sync(0xffffffffu, sD, 1);

    if (grow < NN) {
        const uint4* src = reinterpret_cast<const uint4*>(hpk);
        uint4* dst = reinterpret_cast<uint4*>(&h[(long)grow * HD + hf * 32]);
#pragma unroll
        for (int q = 0; q < 4; q++) dst[q] = src[q];
        if (hf == 0) { out_as[grow] = sA; out_ad[grow] = sD; }
    }
}

// ---------------- node kernel: single-sweep softmax-aggregate ---------------
// out = sum(exp(e_j) h_j) / sum(exp(e_j)) + bias  (softmax shift-invariance).
// Warp per dst node; 4 edges in flight, 8 lanes x 16B(=8 halves) per edge.
__global__ void node_kernel(const __half* __restrict__ h, const float* __restrict__ as_,
                            const float* __restrict__ ad_, const float* __restrict__ bias,
                            float* __restrict__ outp)
{
    int node = (blockIdx.x * blockDim.x + threadIdx.x) >> 5;
    int lane = threadIdx.x & 31;
    if (node >= NN) return;

    int beg = g_off[node], end = g_off[node + 1];
    float adv = __ldg(&ad_[node]);

    int quarter = lane >> 3;   // which of 4 in-flight edges
    int ch      = lane & 7;    // 8 halves at byte offset ch*16

    float den = 0.f;
    float acc[8];
#pragma unroll
    for (int k = 0; k < 8; k++) acc[k] = 0.f;

    for (int base = beg; base < end; base += 32) {
        int j = base + lane;
        int s = 0; float ex = 0.f;
        if (j < end) {
            s = g_csrc[j];
            float e = __ldg(&as_[s]) + adv;
            e = e > 0.f ? e : 0.2f * e;
            ex = __expf(e);
            den += ex;
        }
        int cnt = min(32, end - base);
        for (int t = 0; t < cnt; t += 4) {
            int tt = t + quarter;
            int   ss = __shfl_sync(0xffffffffu, s, tt & 31);
            float ee = __shfl_sync(0xffffffffu, ex, tt & 31);
            if (tt < cnt) {
                float4 raw = *reinterpret_cast<const float4*>(
                    reinterpret_cast<const char*>(h) + (long)ss * 128 + ch * 16);
                const __half2* hp = reinterpret_cast<const __half2*>(&raw);
#pragma unroll
                for (int k = 0; k < 4; k++) {
                    float2 f = __half22float2(hp[k]);
                    acc[2 * k + 0] = fmaf(ee, f.x, acc[2 * k + 0]);
                    acc[2 * k + 1] = fmaf(ee, f.y, acc[2 * k + 1]);
                }
            }
        }
    }
    // reduce den across warp; combine the 4 edge-quarters of acc
#pragma unroll
    for (int o = 16; o >= 1; o >>= 1) den += __shfl_xor_sync(0xffffffffu, den, o);
#pragma unroll
    for (int k = 0; k < 8; k++) {
        acc[k] += __shfl_xor_sync(0xffffffffu, acc[k], 8);
        acc[k] += __shfl_xor_sync(0xffffffffu, acc[k], 16);
    }

    if (quarter == 0) {
        float inv = 1.f / den;
        float4 b0 = *reinterpret_cast<const float4*>(&bias[ch * 8 + 0]);
        float4 b1 = *reinterpret_cast<const float4*>(&bias[ch * 8 + 4]);
        float4 o0 = make_float4(fmaf(acc[0], inv, b0.x), fmaf(acc[1], inv, b0.y),
                                fmaf(acc[2], inv, b0.z), fmaf(acc[3], inv, b0.w));
        float4 o1 = make_float4(fmaf(acc[4], inv, b1.x), fmaf(acc[5], inv, b1.y),
                                fmaf(acc[6], inv, b1.z), fmaf(acc[7], inv, b1.w));
        *reinterpret_cast<float4*>(&outp[(long)node * HD + ch * 8 + 0]) = o0;
        *reinterpret_cast<float4*>(&outp[(long)node * HD + ch * 8 + 4]) = o1;
    }
}

// ---------------- launch -----------------------------------------------------
extern "C" void kernel_launch(void* const* d_in, const int* in_sizes, int n_in,
                              void* d_out, int out_size)
{
    const float* x   = (const float*)d_in[0];
    const void*  ei  = d_in[1];
    const float* W1  = (const float*)d_in[2];
    const float* a1s = (const float*)d_in[3];
    const float* a1d = (const float*)d_in[4];
    const float* b1  = (const float*)d_in[5];
    const float* W2  = (const float*)d_in[6];
    const float* a2s = (const float*)d_in[7];
    const float* a2d = (const float*)d_in[8];
    const float* b2  = (const float*)d_in[9];
    float* out = (float*)d_out;

    __half *p_h, *p_wt1, *p_wt2;
    float *p_agg1, *p_as, *p_ad;
    cudaGetSymbolAddress((void**)&p_h,    g_hh);
    cudaGetSymbolAddress((void**)&p_agg1, g_agg1);
    cudaGetSymbolAddress((void**)&p_as,   g_as);
    cudaGetSymbolAddress((void**)&p_ad,   g_ad);
    cudaGetSymbolAddress((void**)&p_wt1,  g_Wth1);
    cudaGetSymbolAddress((void**)&p_wt2,  g_Wth2);

    const int TB = 256;
    const int GB_E    = (ETOT + TB - 1) / TB;
    const int GB_N    = (NN + TB - 1) / TB;
    const int GB_GEMM = (NN + 63) / 64;
    const int GB_NODE = (NN * 32 + TB - 1) / TB;

    // order chosen so gemm1 is the 4th launch (ncu's capture slot)
    setup_kernel<<<GB_N, TB>>>(W1, W2);
    detect_kernel<<<1, 256>>>((const unsigned*)ei);
    deg_kernel<<<GB_E, TB>>>(ei);
    gemm_kernel<128, false><<<GB_GEMM, 128>>>(x, p_wt1, a1s, a1d, p_h, p_as, p_ad);
    scanA_kernel<<<NBLK, 1024>>>();
    scanB_kernel<<<1, 32>>>();
    scanC_kernel<<<NBLK, 1024>>>();
    scatter_kernel<<<GB_E, TB>>>(ei);

    node_kernel<<<GB_NODE, TB>>>(p_h, p_as, p_ad, b1, p_agg1);
    gemm_kernel<64, true><<<GB_GEMM, 128>>>(p_agg1, p_wt2, a2s, a2d, p_h, p_as, p_ad);
    node_kernel<<<GB_NODE, TB>>>(p_h, p_as, p_ad, b2, out);
}

// round 17
// speedup vs baseline: 2.6198x; 1.2645x over previous
#include <cuda_runtime.h>
#include <cuda_fp16.h>
#include <mma.h>
using namespace nvcuda;

// Problem constants
#define NN   50000
#define EE   800000
#define ETOT 850000   // EE + NN self loops
#define HD   64
#define NBLK 49       // ceil(NN / 1024)

// ---------------- scratch (static device globals; no allocation) ------------
static __device__ int    g_csrc[ETOT];     // CSR-ordered src indices
static __device__ int    g_deg[NN];
static __device__ int    g_off[NN + 1];
static __device__ int    g_cur[NN];
static __device__ int    g_part[64];
static __device__ __half g_hh[NN * HD];    // transformed features (fp16, gather operand)
static __device__ float  g_agg1[NN * HD];  // layer-1 output (incl. bias), fp32
static __device__ float  g_as[NN];
static __device__ float  g_ad[NN];
static __device__ __half g_Wth1[128 * 64]; // W1^T in fp16: [k][c]
static __device__ __half g_Wth2[64 * 64];  // W2^T in fp16
static __device__ int    g_is64;

// ---------------- setup: zero counters + transpose/convert weights ----------
__global__ void setup_kernel(const float* __restrict__ W1, const float* __restrict__ W2) {
    int i = blockIdx.x * blockDim.x + threadIdx.x;
    if (i < NN) { g_deg[i] = 0; g_cur[i] = 0; }
    if (i < 128 * 64) { int k = i % 128, c = i / 128; g_Wth1[k * 64 + c] = __float2half(W1[c * 128 + k]); }
    if (i < 64 * 64)  { int k = i % 64,  c = i / 64;  g_Wth2[k * 64 + c] = __float2half(W2[c * 64 + k]); }
}

__global__ void detect_kernel(const unsigned* __restrict__ w) {
    __shared__ int s;
    if (threadIdx.x == 0) s = 0;
    __syncthreads();
    // int64 values < 2^31 -> every odd 32-bit word is 0.
    if (w[2 * threadIdx.x + 1] != 0u) atomicOr(&s, 1);
    __syncthreads();
    if (threadIdx.x == 0) g_is64 = (s == 0);
}

// degree histogram: reads only the dst row of edge_index (+ self loops)
__global__ void deg_kernel(const void* __restrict__ ei) {
    int i = blockIdx.x * blockDim.x + threadIdx.x;
    if (i >= ETOT) return;
    int d;
    if (i >= EE) d = i - EE;
    else if (g_is64) d = (int)((const long long*)ei)[EE + i];
    else             d = ((const int*)ei)[EE + i];
    atomicAdd(&g_deg[d], 1);
}

// warp-shuffle block scan (inclusive) -> g_off[i+1], block sums -> g_part
__global__ void scanA_kernel() {
    __shared__ int wsum[32];
    int tid = threadIdx.x;
    int i = blockIdx.x * 1024 + tid;
    int x = (i < NN) ? g_deg[i] : 0;
#pragma unroll
    for (int o = 1; o < 32; o <<= 1) {
        int t = __shfl_up_sync(0xffffffffu, x, o);
        if ((tid & 31) >= o) x += t;
    }
    if ((tid & 31) == 31) wsum[tid >> 5] = x;
    __syncthreads();
    if (tid < 32) {
        int w = wsum[tid];
#pragma unroll
        for (int o = 1; o < 32; o <<= 1) {
            int t = __shfl_up_sync(0xffffffffu, w, o);
            if (tid >= o) w += t;
        }
        wsum[tid] = w;
    }
    __syncthreads();
    if (tid >= 32) x += wsum[(tid >> 5) - 1];
    if (i < NN) g_off[i + 1] = x;
    if (tid == 1023) g_part[blockIdx.x] = x;
}
__global__ void scanB_kernel() {
    if (threadIdx.x == 0) {
        int acc = 0;
        for (int b = 0; b < NBLK; b++) { int t = g_part[b]; g_part[b] = acc; acc += t; }
    }
}
__global__ void scanC_kernel() {
    int i = blockIdx.x * 1024 + threadIdx.x;
    if (i < NN) g_off[i + 1] += g_part[blockIdx.x];
    if (i == 0) g_off[0] = 0;
}

// scatter src indices into CSR order (re-decodes edge list directly)
__global__ void scatter_kernel(const void* __restrict__ ei) {
    int i = blockIdx.x * blockDim.x + threadIdx.x;
    if (i >= ETOT) return;
    int s, d;
    if (i >= EE) { s = i - EE; d = s; }
    else if (g_is64) {
        const long long* p = (const long long*)ei;
        s = (int)p[i]; d = (int)p[EE + i];
    } else {
        const int* p = (const int*)ei;
        s = p[i]; d = p[EE + i];
    }
    int pos = g_off[d] + atomicAdd(&g_cur[d], 1);
    g_csrc[pos] = s;
}

// ---------------- WMMA GEMM: h = x @ W^T (fp16 in/out, fp32 accum) ----------
// 128 rows / block of 256 threads (8 warps). Warp w computes rows 16w..16w+15
// against all 64 output cols. Padded smem leading dims kill ldmatrix bank
// conflicts: A ldm=K+8, W ldm=72, C ldm=68.
template <int K, bool RELU>
__global__ void gemm_kernel(const float* __restrict__ x, const __half* __restrict__ Wth,
                            const float* __restrict__ asrc, const float* __restrict__ adst,
                            __half* __restrict__ h, float* __restrict__ out_as,
                            float* __restrict__ out_ad)
{
    constexpr int AP = K + 8;    // A tile leading dim (halves)
    constexpr int WP = 72;       // W tile leading dim (halves)
    constexpr int CP = 68;       // C tile leading dim (floats)
    __shared__ __align__(16) __half sW[K * WP];
    __shared__ __align__(16) union SB {
        __half xin[128 * AP];
        float  out[128 * CP];
    } sb;

    int tid  = threadIdx.x;
    int wid  = tid >> 5;
    int row0 = blockIdx.x * 128;

    // load W tile (fp16), padded rows
    for (int i = tid; i < K * 64 / 8; i += 256) {
        int k = i / 8, q = i % 8;   // 8 halves per chunk
        *reinterpret_cast<uint4*>(&sW[k * WP + q * 8]) =
            reinterpret_cast<const uint4*>(Wth)[i];
    }

    // load x tile: float4 -> half2 pairs, padded rows
    for (int i = tid; i < 128 * (K / 4); i += 256) {
        int r = i / (K / 4), kq = i % (K / 4);
        int row = row0 + r;
        float4 v = make_float4(0.f, 0.f, 0.f, 0.f);
        if (row < NN) {
            v = *reinterpret_cast<const float4*>(&x[(long)row * K + kq * 4]);
            if (RELU) {
                v.x = fmaxf(v.x, 0.f); v.y = fmaxf(v.y, 0.f);
                v.z = fmaxf(v.z, 0.f); v.w = fmaxf(v.w, 0.f);
            }
        }
        __half2 p[2];
        p[0] = __floats2half2_rn(v.x, v.y);
        p[1] = __floats2half2_rn(v.z, v.w);
        *reinterpret_cast<uint2*>(&sb.xin[r * AP + kq * 4]) = *reinterpret_cast<const uint2*>(p);
    }
    __syncthreads();

    // MMA mainloop: each warp does 16 rows x 64 cols
    wmma::fragment<wmma::accumulator, 16, 16, 16, float> acc[4];
#pragma unroll
    for (int n = 0; n < 4; n++) wmma::fill_fragment(acc[n], 0.f);

#pragma unroll
    for (int k = 0; k < K; k += 16) {
        wmma::fragment<wmma::matrix_a, 16, 16, 16, __half, wmma::row_major> af;
        wmma::load_matrix_sync(af, &sb.xin[wid * 16 * AP + k], AP);
#pragma unroll
        for (int n = 0; n < 4; n++) {
            wmma::fragment<wmma::matrix_b, 16, 16, 16, __half, wmma::row_major> bf;
            wmma::load_matrix_sync(bf, &sW[k * WP + n * 16], WP);
            wmma::mma_sync(acc[n], af, bf, acc[n]);
        }
    }
    __syncthreads();   // xin no longer needed; reuse as out

#pragma unroll
    for (int n = 0; n < 4; n++)
        wmma::store_matrix_sync(&sb.out[wid * 16 * CP + n * 16], acc[n], CP, wmma::mem_row_major);
    __syncthreads();

    // Epilogue: 2 threads per row (half each); fp16 h store + alpha dots
    int r  = tid >> 1;
    int hf = tid & 1;
    int grow = row0 + r;

    float sA = 0.f, sD = 0.f;
    __half2 hpk[16];
#pragma unroll
    for (int i = 0; i < 16; i++) {
        int cc = ((r + i) & 15) * 2;          // staggered even column within half
        int c  = hf * 32 + cc;
        float2 v = *reinterpret_cast<const float2*>(&sb.out[r * CP + c]);
        sA = fmaf(v.x, __ldg(&asrc[c]), fmaf(v.y, __ldg(&asrc[c + 1]), sA));
        sD = fmaf(v.x, __ldg(&adst[c]), fmaf(v.y, __ldg(&adst[c + 1]), sD));
        hpk[cc >> 1] = __floats2half2_rn(v.x, v.y);
    }
    // combine the two halves of each row
    sA += __shfl_xor_sync(0xffffffffu, sA, 1);
    sD += __shfl_xor_sync(0xffffffffu, sD, 1);

    if (grow < NN) {
        const uint4* src = reinterpret_cast<const uint4*>(hpk);
        uint4* dst = reinterpret_cast<uint4*>(&h[(long)grow * HD + hf * 32]);
#pragma unroll
        for (int q = 0; q < 4; q++) dst[q] = src[q];
        if (hf == 0) { out_as[grow] = sA; out_ad[grow] = sD; }
    }
}

// ---------------- node kernel: single-sweep softmax-aggregate ---------------
// out = sum(exp(e_j) h_j) / sum(exp(e_j)) + bias  (softmax shift-invariance).
// Warp per dst node; 4 edges in flight, 8 lanes x 16B(=8 halves) per edge.
__global__ void node_kernel(const __half* __restrict__ h, const float* __restrict__ as_,
                            const float* __restrict__ ad_, const float* __restrict__ bias,
                            float* __restrict__ outp)
{
    int node = (blockIdx.x * blockDim.x + threadIdx.x) >> 5;
    int lane = threadIdx.x & 31;
    if (node >= NN) return;

    int beg = g_off[node], end = g_off[node + 1];
    float adv = __ldg(&ad_[node]);

    int quarter = lane >> 3;   // which of 4 in-flight edges
    int ch      = lane & 7;    // 8 halves at byte offset ch*16

    float den = 0.f;
    float acc[8];
#pragma unroll
    for (int k = 0; k < 8; k++) acc[k] = 0.f;

    for (int base = beg; base < end; base += 32) {
        int j = base + lane;
        int s = 0; float ex = 0.f;
        if (j < end) {
            s = g_csrc[j];
            float e = __ldg(&as_[s]) + adv;
            e = e > 0.f ? e : 0.2f * e;
            ex = __expf(e);
            den += ex;
        }
        int cnt = min(32, end - base);
        for (int t = 0; t < cnt; t += 4) {
            int tt = t + quarter;
            int   ss = __shfl_sync(0xffffffffu, s, tt & 31);
            float ee = __shfl_sync(0xffffffffu, ex, tt & 31);
            if (tt < cnt) {
                float4 raw = *reinterpret_cast<const float4*>(
                    reinterpret_cast<const char*>(h) + (long)ss * 128 + ch * 16);
                const __half2* hp = reinterpret_cast<const __half2*>(&raw);
#pragma unroll
                for (int k = 0; k < 4; k++) {
                    float2 f = __half22float2(hp[k]);
                    acc[2 * k + 0] = fmaf(ee, f.x, acc[2 * k + 0]);
                    acc[2 * k + 1] = fmaf(ee, f.y, acc[2 * k + 1]);
                }
            }
        }
    }
    // reduce den across warp; combine the 4 edge-quarters of acc
#pragma unroll
    for (int o = 16; o >= 1; o >>= 1) den += __shfl_xor_sync(0xffffffffu, den, o);
#pragma unroll
    for (int k = 0; k < 8; k++) {
        acc[k] += __shfl_xor_sync(0xffffffffu, acc[k], 8);
        acc[k] += __shfl_xor_sync(0xffffffffu, acc[k], 16);
    }

    if (quarter == 0) {
        float inv = 1.f / den;
        float4 b0 = *reinterpret_cast<const float4*>(&bias[ch * 8 + 0]);
        float4 b1 = *reinterpret_cast<const float4*>(&bias[ch * 8 + 4]);
        float4 o0 = make_float4(fmaf(acc[0], inv, b0.x), fmaf(acc[1], inv, b0.y),
                                fmaf(acc[2], inv, b0.z), fmaf(acc[3], inv, b0.w));
        float4 o1 = make_float4(fmaf(acc[4], inv, b1.x), fmaf(acc[5], inv, b1.y),
                                fmaf(acc[6], inv, b1.z), fmaf(acc[7], inv, b1.w));
        *reinterpret_cast<float4*>(&outp[(long)node * HD + ch * 8 + 0]) = o0;
        *reinterpret_cast<float4*>(&outp[(long)node * HD + ch * 8 + 4]) = o1;
    }
}

// ---------------- launch -----------------------------------------------------
extern "C" void kernel_launch(void* const* d_in, const int* in_sizes, int n_in,
                              void* d_out, int out_size)
{
    const float* x   = (const float*)d_in[0];
    const void*  ei  = d_in[1];
    const float* W1  = (const float*)d_in[2];
    const float* a1s = (const float*)d_in[3];
    const float* a1d = (const float*)d_in[4];
    const float* b1  = (const float*)d_in[5];
    const float* W2  = (const float*)d_in[6];
    const float* a2s = (const float*)d_in[7];
    const float* a2d = (const float*)d_in[8];
    const float* b2  = (const float*)d_in[9];
    float* out = (float*)d_out;

    __half *p_h, *p_wt1, *p_wt2;
    float *p_agg1, *p_as, *p_ad;
    cudaGetSymbolAddress((void**)&p_h,    g_hh);
    cudaGetSymbolAddress((void**)&p_agg1, g_agg1);
    cudaGetSymbolAddress((void**)&p_as,   g_as);
    cudaGetSymbolAddress((void**)&p_ad,   g_ad);
    cudaGetSymbolAddress((void**)&p_wt1,  g_Wth1);
    cudaGetSymbolAddress((void**)&p_wt2,  g_Wth2);

    const int TB = 256;
    const int GB_E    = (ETOT + TB - 1) / TB;
    const int GB_N    = (NN + TB - 1) / TB;
    const int GB_GEMM = (NN + 127) / 128;
    const int GB_NODE = (NN * 32 + TB - 1) / TB;

    // order chosen so gemm1 is the 4th launch (ncu's capture slot)
    setup_kernel<<<GB_N, TB>>>(W1, W2);
    detect_kernel<<<1, 256>>>((const unsigned*)ei);
    deg_kernel<<<GB_E, TB>>>(ei);
    gemm_kernel<128, false><<<GB_GEMM, 256>>>(x, p_wt1, a1s, a1d, p_h, p_as, p_ad);
    scanA_kernel<<<NBLK, 1024>>>();
    scanB_kernel<<<1, 32>>>();
    scanC_kernel<<<NBLK, 1024>>>();
    scatter_kernel<<<GB_E, TB>>>(ei);

    node_kernel<<<GB_NODE, TB>>>(p_h, p_as, p_ad, b1, p_agg1);
    gemm_kernel<64, true><<<GB_GEMM, 256>>>(p_agg1, p_wt2, a2s, a2d, p_h, p_as, p_ad);
    node_kernel<<<GB_NODE, TB>>>(p_h, p_as, p_ad, b2, out);
}